// round 1
// baseline (speedup 1.0000x reference)
#include <cuda_runtime.h>
#include <math.h>

// Problem dims
#define T_STEPS 2048
#define BATCH   64
#define DIN     512
#define HDIM    512
#define G4      2048            // 4*H
#define M_ROWS  131072          // T*B

// Scratch (device globals: allocation-free contract)
__device__ float g_xproj[268435456];   // [T][B][4H] fp32 = 1 GiB
__device__ float g_h[2][BATCH * HDIM]; // ping-pong hidden state
__device__ unsigned long long g_arrive  = 0ULL;
__device__ unsigned long long g_release = 0ULL;

// ---------------------------------------------------------------------------
// Kernel 1: x_proj = X @ Wx + bx    (M=131072, N=2048, K=512), fp32 SGEMM
// 128x128 tile, K-step 8, 256 threads, 8x8 per thread, double-buffered smem.
// ---------------------------------------------------------------------------
__global__ __launch_bounds__(256) void sgemm_xproj(
    const float* __restrict__ A,     // X  [M][512]
    const float* __restrict__ B,     // Wx [512][2048]
    const float* __restrict__ bias)  // bx [2048]
{
    __shared__ float As[2][8][128];
    __shared__ float Bs[2][8][128];
    const int K = 512, N = 2048;

    const int bm = blockIdx.y * 128;
    const int bn = blockIdx.x * 128;
    const int tid = threadIdx.x;

    const int a_row = tid >> 1, a_col = (tid & 1) << 2;   // 128 x 8 tile of A
    const int b_row = tid >> 5, b_col = (tid & 31) << 2;  // 8 x 128 tile of B

    const float* Ap = A + (size_t)(bm + a_row) * K + a_col;
    const float* Bp = B + (size_t)b_row * N + bn + b_col;

    // preload tile 0
    float4 av = *(const float4*)Ap;
    float4 bv = *(const float4*)Bp;
    As[0][a_col + 0][a_row] = av.x;
    As[0][a_col + 1][a_row] = av.y;
    As[0][a_col + 2][a_row] = av.z;
    As[0][a_col + 3][a_row] = av.w;
    *(float4*)&Bs[0][b_row][b_col] = bv;
    __syncthreads();

    const int tx = tid & 15, ty = tid >> 4;

    float acc[8][8];
#pragma unroll
    for (int i = 0; i < 8; i++)
#pragma unroll
        for (int j = 0; j < 8; j++) acc[i][j] = 0.f;

    for (int kt = 0; kt < 64; kt++) {
        const int cur = kt & 1;
        if (kt < 63) {
            av = *(const float4*)(Ap + (kt + 1) * 8);
            bv = *(const float4*)(Bp + (size_t)(kt + 1) * 8 * N);
        }
#pragma unroll
        for (int k = 0; k < 8; k++) {
            float a[8], b[8];
#pragma unroll
            for (int i = 0; i < 8; i++) a[i] = As[cur][k][ty * 8 + i];
#pragma unroll
            for (int j = 0; j < 8; j++) b[j] = Bs[cur][k][tx * 8 + j];
#pragma unroll
            for (int i = 0; i < 8; i++)
#pragma unroll
                for (int j = 0; j < 8; j++)
                    acc[i][j] = fmaf(a[i], b[j], acc[i][j]);
        }
        if (kt < 63) {
            const int nxt = cur ^ 1;
            As[nxt][a_col + 0][a_row] = av.x;
            As[nxt][a_col + 1][a_row] = av.y;
            As[nxt][a_col + 2][a_row] = av.z;
            As[nxt][a_col + 3][a_row] = av.w;
            *(float4*)&Bs[nxt][b_row][b_col] = bv;
            __syncthreads();
        }
    }

    float bvals[8];
#pragma unroll
    for (int j = 0; j < 8; j++) bvals[j] = bias[bn + tx * 8 + j];

#pragma unroll
    for (int i = 0; i < 8; i++) {
        float* crow = g_xproj + (size_t)(bm + ty * 8 + i) * N + bn + tx * 8;
        float4 v0, v1;
        v0.x = acc[i][0] + bvals[0]; v0.y = acc[i][1] + bvals[1];
        v0.z = acc[i][2] + bvals[2]; v0.w = acc[i][3] + bvals[3];
        v1.x = acc[i][4] + bvals[4]; v1.y = acc[i][5] + bvals[5];
        v1.z = acc[i][6] + bvals[6]; v1.w = acc[i][7] + bvals[7];
        *(float4*)crow       = v0;
        *(float4*)(crow + 4) = v1;
    }
}

// ---------------------------------------------------------------------------
// Kernel 2: persistent sequential recurrence.
// 128 CTAs x 256 threads. CTA owns 4 h-columns (and their 4 gate columns).
// Wh slice (512x16) lives in smem for the whole run; c-state in registers;
// h broadcast through a ping-pong device buffer with a software grid barrier.
// ---------------------------------------------------------------------------
#define NBLK 128
#define HS_PITCH 516  // 512 + 4 pad: conflict-free float4 rows

__device__ __forceinline__ void grid_barrier() {
    __syncthreads();
    if (threadIdx.x == 0) {
        __threadfence();
        unsigned long long t = atomicAdd(&g_arrive, 1ULL) + 1ULL;
        unsigned long long n = (unsigned long long)NBLK;
        unsigned long long target = ((t + n - 1ULL) / n) * n;
        if (t == target) {
            atomicMax(&g_release, target);
        } else {
            unsigned long long r;
            do {
                asm volatile("ld.volatile.global.u64 %0, [%1];"
                             : "=l"(r) : "l"(&g_release));
            } while (r < target);
        }
        __threadfence();
    }
    __syncthreads();
}

__global__ __launch_bounds__(256) void lstm_seq(
    const float* __restrict__ Wh,   // [512][2048]
    const float* __restrict__ bh,   // [2048]
    float* __restrict__ out)        // [2][64][512]
{
    extern __shared__ float smem[];
    float* h_s  = smem;                          // 64 * 516
    float* wh_s = smem + BATCH * HS_PITCH;       // 512 * 16, layout [k][q][g]
    float* bh_s = wh_s + 512 * 16;               // 16, layout [q][g]

    const int tid  = threadIdx.x;
    const int cta  = blockIdx.x;
    const int c0   = cta * 4;        // first owned h-column
    const int b    = tid >> 2;       // batch row (0..63)
    const int q    = tid & 3;        // owned column within CTA (0..3)
    const int colg = c0 + q;         // global h-column

    // Load Wh slice: wh_s[k*16 + q*4 + g] = Wh[k][g*512 + c0 + q]
    for (int j = tid; j < 512 * 16; j += 256) {
        int k = j >> 4, r = j & 15;
        int qq = (r >> 2), gg = (r & 3);
        wh_s[j] = Wh[(size_t)k * G4 + gg * HDIM + c0 + qq];
    }
    if (tid < 16) bh_s[tid] = bh[(tid & 3) * HDIM + c0 + (tid >> 2)];

    // Zero h buffer 0 (h_0 = 0)
    g_h[0][cta * 256 + tid] = 0.f;

    grid_barrier();

    float c_st = 0.f, hsum = 0.f, csum = 0.f;

    for (int t = 0; t < T_STEPS; t++) {
        const int rb = t & 1;

        // Broadcast h_{t-1} into smem (coalesced float4)
        const float4* hg = (const float4*)g_h[rb];
        for (int v = tid; v < (BATCH * HDIM) / 4; v += 256) {
            float4 hv = hg[v];
            int bb = v >> 7;               // (v*4)/512
            int cc = (v & 127) << 2;
            *(float4*)&h_s[bb * HS_PITCH + cc] = hv;
        }
        __syncthreads();

        // Prefetch x_proj gates for this (t, b, colg) early (DRAM latency)
        const float* xr = g_xproj + (size_t)t * (BATCH * G4) + (size_t)b * G4 + colg;
        const float xp0 = xr[0];
        const float xp1 = xr[HDIM];
        const float xp2 = xr[2 * HDIM];
        const float xp3 = xr[3 * HDIM];

        float a0 = 0.f, a1 = 0.f, a2 = 0.f, a3 = 0.f;
        const float* hrow = h_s + b * HS_PITCH;
        const float* wq   = wh_s + q * 4;
#pragma unroll 2
        for (int k = 0; k < HDIM; k += 4) {
            float4 hv = *(const float4*)(hrow + k);
            float4 w0 = *(const float4*)(wq + (k + 0) * 16);
            float4 w1 = *(const float4*)(wq + (k + 1) * 16);
            float4 w2 = *(const float4*)(wq + (k + 2) * 16);
            float4 w3 = *(const float4*)(wq + (k + 3) * 16);
            a0 = fmaf(hv.x, w0.x, a0); a1 = fmaf(hv.x, w0.y, a1);
            a2 = fmaf(hv.x, w0.z, a2); a3 = fmaf(hv.x, w0.w, a3);
            a0 = fmaf(hv.y, w1.x, a0); a1 = fmaf(hv.y, w1.y, a1);
            a2 = fmaf(hv.y, w1.z, a2); a3 = fmaf(hv.y, w1.w, a3);
            a0 = fmaf(hv.z, w2.x, a0); a1 = fmaf(hv.z, w2.y, a1);
            a2 = fmaf(hv.z, w2.z, a2); a3 = fmaf(hv.z, w2.w, a3);
            a0 = fmaf(hv.w, w3.x, a0); a1 = fmaf(hv.w, w3.y, a1);
            a2 = fmaf(hv.w, w3.z, a2); a3 = fmaf(hv.w, w3.w, a3);
        }

        const float gi = a0 + bh_s[q * 4 + 0] + xp0;
        const float gf = a1 + bh_s[q * 4 + 1] + xp1;
        const float go = a2 + bh_s[q * 4 + 2] + xp2;
        const float gz = a3 + bh_s[q * 4 + 3] + xp3;

        const float iv = 1.f / (1.f + __expf(-gi));
        const float fv = 1.f / (1.f + __expf(-gf));
        const float ov = 1.f / (1.f + __expf(-go));
        const float zv = tanhf(gz);

        c_st = fmaf(iv, zv, fv * c_st);
        const float hv_ = ov * tanhf(c_st);

        hsum += hv_;
        csum += c_st;

        g_h[rb ^ 1][b * HDIM + colg] = hv_;

        grid_barrier();
    }

    const float inv = 1.0f / (float)T_STEPS;
    out[b * HDIM + colg]               = hsum * inv;
    out[BATCH * HDIM + b * HDIM + colg] = csum * inv;
}

// ---------------------------------------------------------------------------
extern "C" void kernel_launch(void* const* d_in, const int* in_sizes, int n_in,
                              void* d_out, int out_size) {
    const float* X  = (const float*)d_in[0];
    const float* Wx = (const float*)d_in[1];
    const float* bx = (const float*)d_in[2];
    const float* Wh = (const float*)d_in[3];
    const float* bh = (const float*)d_in[4];
    float* out = (float*)d_out;

    const int smem_bytes = (BATCH * HS_PITCH + 512 * 16 + 16) * (int)sizeof(float);
    cudaFuncSetAttribute(lstm_seq, cudaFuncAttributeMaxDynamicSharedMemorySize,
                         smem_bytes);

    dim3 gemm_grid(2048 / 128, M_ROWS / 128);  // (16, 1024)
    sgemm_xproj<<<gemm_grid, 256>>>(X, Wx, bx);

    lstm_seq<<<NBLK, 256, smem_bytes>>>(Wh, bh, out);
}

// round 2
// speedup vs baseline: 1.7412x; 1.7412x over previous
#include <cuda_runtime.h>
#include <math.h>

// Problem dims
#define T_STEPS 2048
#define BATCH   64
#define DIN     512
#define HDIM    512
#define G4      2048            // 4*H
#define M_ROWS  131072          // T*B
#define NBLK    128

typedef unsigned long long u64;

// Scratch (device globals: allocation-free contract)
__device__ float g_xproj[268435456];   // [T][B][4H] fp32 = 1 GiB
__device__ float g_h[2][BATCH * HDIM]; // ping-pong hidden state
__device__ unsigned long long g_arrive  = 0ULL;
__device__ unsigned long long g_release = 0ULL;

// ---------------------------------------------------------------------------
// packed fp32x2 helpers (sm_103a: fma.rn.f32x2 — 2 MACs per instruction)
// ---------------------------------------------------------------------------
__device__ __forceinline__ u64 pack2(float lo, float hi) {
    u64 r;
    asm("mov.b64 %0, {%1, %2};" : "=l"(r) : "f"(lo), "f"(hi));
    return r;
}
__device__ __forceinline__ void unpack2(u64 v, float& lo, float& hi) {
    asm("mov.b64 {%0, %1}, %2;" : "=f"(lo), "=f"(hi) : "l"(v));
}
__device__ __forceinline__ u64 fma2(u64 a, u64 b, u64 c) {
    u64 d;
    asm("fma.rn.f32x2 %0, %1, %2, %3;" : "=l"(d) : "l"(a), "l"(b), "l"(c));
    return d;
}

// ---------------------------------------------------------------------------
// Kernel 1: x_proj = X @ Wx + bx   (M=131072, N=2048, K=512)
// 128x128 tile, 256 threads, 8x8 per thread, f32x2 accumulation (acc = 8x4
// column-pairs), double-buffered smem.
// ---------------------------------------------------------------------------
__global__ __launch_bounds__(256) void sgemm_xproj(
    const float* __restrict__ A,     // X  [M][512]
    const float* __restrict__ B,     // Wx [512][2048]
    const float* __restrict__ bias)  // bx [2048]
{
    __shared__ float As[2][8][128];
    __shared__ float Bs[2][8][128];
    const int K = 512, N = 2048;

    const int bm = blockIdx.y * 128;
    const int bn = blockIdx.x * 128;
    const int tid = threadIdx.x;

    const int a_row = tid >> 1, a_col = (tid & 1) << 2;   // 128 x 8 tile of A
    const int b_row = tid >> 5, b_col = (tid & 31) << 2;  // 8 x 128 tile of B

    const float* Ap = A + (size_t)(bm + a_row) * K + a_col;
    const float* Bp = B + (size_t)b_row * N + bn + b_col;

    // preload tile 0
    float4 av = *(const float4*)Ap;
    float4 bv = *(const float4*)Bp;
    As[0][a_col + 0][a_row] = av.x;
    As[0][a_col + 1][a_row] = av.y;
    As[0][a_col + 2][a_row] = av.z;
    As[0][a_col + 3][a_row] = av.w;
    *(float4*)&Bs[0][b_row][b_col] = bv;
    __syncthreads();

    const int tx = tid & 15, ty = tid >> 4;

    u64 acc[8][4];   // 8 rows x 4 column-pairs (f32x2)
#pragma unroll
    for (int i = 0; i < 8; i++)
#pragma unroll
        for (int j = 0; j < 4; j++) acc[i][j] = 0ULL;

    for (int kt = 0; kt < 64; kt++) {
        const int cur = kt & 1;
        if (kt < 63) {
            av = *(const float4*)(Ap + (kt + 1) * 8);
            bv = *(const float4*)(Bp + (size_t)(kt + 1) * 8 * N);
        }
#pragma unroll
        for (int k = 0; k < 8; k++) {
            float4 a0 = *(const float4*)&As[cur][k][ty * 8];
            float4 a1 = *(const float4*)&As[cur][k][ty * 8 + 4];
            ulonglong2 b01 = *(const ulonglong2*)&Bs[cur][k][tx * 8];
            ulonglong2 b23 = *(const ulonglong2*)&Bs[cur][k][tx * 8 + 4];
            u64 bb0 = b01.x, bb1 = b01.y, bb2 = b23.x, bb3 = b23.y;
            float aa[8] = {a0.x, a0.y, a0.z, a0.w, a1.x, a1.y, a1.z, a1.w};
#pragma unroll
            for (int i = 0; i < 8; i++) {
                u64 ad = pack2(aa[i], aa[i]);
                acc[i][0] = fma2(ad, bb0, acc[i][0]);
                acc[i][1] = fma2(ad, bb1, acc[i][1]);
                acc[i][2] = fma2(ad, bb2, acc[i][2]);
                acc[i][3] = fma2(ad, bb3, acc[i][3]);
            }
        }
        if (kt < 63) {
            const int nxt = cur ^ 1;
            As[nxt][a_col + 0][a_row] = av.x;
            As[nxt][a_col + 1][a_row] = av.y;
            As[nxt][a_col + 2][a_row] = av.z;
            As[nxt][a_col + 3][a_row] = av.w;
            *(float4*)&Bs[nxt][b_row][b_col] = bv;
            __syncthreads();
        }
    }

    float bvals[8];
#pragma unroll
    for (int j = 0; j < 8; j++) bvals[j] = bias[bn + tx * 8 + j];

#pragma unroll
    for (int i = 0; i < 8; i++) {
        float c[8];
#pragma unroll
        for (int j = 0; j < 4; j++) unpack2(acc[i][j], c[2 * j], c[2 * j + 1]);
        float* crow = g_xproj + (size_t)(bm + ty * 8 + i) * N + bn + tx * 8;
        float4 v0, v1;
        v0.x = c[0] + bvals[0]; v0.y = c[1] + bvals[1];
        v0.z = c[2] + bvals[2]; v0.w = c[3] + bvals[3];
        v1.x = c[4] + bvals[4]; v1.y = c[5] + bvals[5];
        v1.z = c[6] + bvals[6]; v1.w = c[7] + bvals[7];
        *(float4*)crow       = v0;
        *(float4*)(crow + 4) = v1;
    }
}

// ---------------------------------------------------------------------------
// Kernel 2: persistent sequential recurrence.
// 128 CTAs x 256 threads. CTA owns 4 h-columns (16 gate-cols).
// Thread coords: ks (16 k-splits), gp (2: which 8 gate-cols), bg (8: which 8
// batches). Per 2k: 8 LDS.64 (h, conflict-free), 4 LDS.128 (pre-paired w,
// conflict-free), 64 fma.rn.f32x2. Split-K reduced in smem in 2 passes,
// final thread (b, hcol) applies gates and owns c-state.
// ---------------------------------------------------------------------------
#define HP    516   // h_s row pitch (floats)
#define WPU   18    // wpair row pitch (in u64: 16 cols + 2 pad)
#define BUFP  548   // reduction buffer pitch per ks (floats)

#define SMEM_H_BYTES   (BATCH * HP * 4)                 // 132096
#define SMEM_W_BYTES   (256 * WPU * 8)                  // 36864
#define SMEM_BUF_BYTES (16 * BUFP * 4)                  // 35072
#define SMEM_TOTAL (SMEM_H_BYTES + SMEM_W_BYTES + SMEM_BUF_BYTES)

__device__ __forceinline__ void grid_barrier() {
    __syncthreads();
    if (threadIdx.x == 0) {
        __threadfence();
        unsigned long long t = atomicAdd(&g_arrive, 1ULL) + 1ULL;
        unsigned long long n = (unsigned long long)NBLK;
        unsigned long long target = ((t + n - 1ULL) / n) * n;
        if (t == target) {
            atomicMax(&g_release, target);
        } else {
            unsigned long long r;
            do {
                asm volatile("ld.volatile.global.u64 %0, [%1];"
                             : "=l"(r) : "l"(&g_release));
            } while (r < target);
        }
        __threadfence();
    }
    __syncthreads();
}

__global__ __launch_bounds__(256, 1) void lstm_seq(
    const float* __restrict__ Wh,   // [512][2048]
    const float* __restrict__ bh,   // [2048]
    float* __restrict__ out)        // [2][64][512]
{
    extern __shared__ char smem[];
    float* h_s = (float*)smem;
    u64*   wp  = (u64*)(smem + SMEM_H_BYTES);
    float* buf = (float*)(smem + SMEM_H_BYTES + SMEM_W_BYTES);

    const int tid = threadIdx.x;
    const int cta = blockIdx.x;
    const int c0  = cta * 4;             // first owned h-column

    const int ks = tid & 15;             // k-split (strided)
    const int gp = (tid >> 4) & 1;       // gate-col octet
    const int bg = tid >> 5;             // batch octet (== warp id)

    // Final identity: one (batch, h-col) per thread
    const int fb = tid >> 2;             // 0..63
    const int fq = tid & 3;              // 0..3
    const int pass_sel = (fb >> 2) & 1;  // which pass reduces this thread

    // --- Build paired Wh in smem: wp[kk*WPU + c] = (Wh[2kk][col], Wh[2kk+1][col])
    // where c = q*4+g, col = g*512 + c0 + q.
    for (int idx = tid; idx < 256 * 16; idx += 256) {
        int kk = idx >> 4, c = idx & 15;
        int q = c >> 2, g = c & 3;
        int col = g * HDIM + c0 + q;
        float lo = Wh[(size_t)(2 * kk) * G4 + col];
        float hi = Wh[(size_t)(2 * kk + 1) * G4 + col];
        wp[kk * WPU + c] = pack2(lo, hi);
    }

    // Per-thread biases for the 4 gates of (fb, c0+fq)
    const float bh_i = bh[0 * HDIM + c0 + fq];
    const float bh_f = bh[1 * HDIM + c0 + fq];
    const float bh_o = bh[2 * HDIM + c0 + fq];
    const float bh_z = bh[3 * HDIM + c0 + fq];

    // Zero h buffer 0 (h_0 = 0); 128*256 threads cover 32768 exactly.
    g_h[0][cta * 256 + tid] = 0.f;

    grid_barrier();

    float c_st = 0.f, hsum = 0.f, csum = 0.f;

    const float* hbase   = h_s + bg * 8 * HP + 2 * ks;
    const u64*   wbase   = wp + ks * WPU + gp * 8;
    float*       stbase  = buf + ks * BUFP + gp * 272 + bg * 32;
    const float* redbase = buf + (fq >> 1) * 272 + (fb >> 3) * 32
                               + (fb & 3) * 8 + (fq & 1) * 4;

    for (int t = 0; t < T_STEPS; t++) {
        const int rb = t & 1;

        // Prefetch this thread's x_proj gates (hidden under the step's work)
        const float* xr = g_xproj + (size_t)t * (BATCH * G4)
                        + (size_t)fb * G4 + c0 + fq;
        const float xp_i = xr[0];
        const float xp_f = xr[HDIM];
        const float xp_o = xr[2 * HDIM];
        const float xp_z = xr[3 * HDIM];

        // Broadcast h_{t-1} into smem (coalesced float4)
        const float4* hg = (const float4*)g_h[rb];
#pragma unroll
        for (int v = tid; v < (BATCH * HDIM) / 4; v += 256) {
            float4 hv = hg[v];
            int bb = v >> 7;
            int cc = (v & 127) << 2;
            *(float4*)&h_s[bb * HP + cc] = hv;
        }
        __syncthreads();

        // --- Main GEMM slice: acc[j][c] over (8 batches x 8 gate-cols),
        // k handled in f32x2 pairs, split-K stride 16 pairs.
        u64 acc[8][8];
#pragma unroll
        for (int j = 0; j < 8; j++)
#pragma unroll
            for (int c = 0; c < 8; c++) acc[j][c] = 0ULL;

#pragma unroll 2
        for (int i = 0; i < 16; i++) {
            const u64* wr = wbase + i * 16 * WPU;
            ulonglong2 p0 = *(const ulonglong2*)(wr + 0);
            ulonglong2 p1 = *(const ulonglong2*)(wr + 2);
            ulonglong2 p2 = *(const ulonglong2*)(wr + 4);
            ulonglong2 p3 = *(const ulonglong2*)(wr + 6);
            u64 w0 = p0.x, w1 = p0.y, w2 = p1.x, w3 = p1.y;
            u64 w4 = p2.x, w5 = p2.y, w6 = p3.x, w7 = p3.y;
            const float* hrow = hbase + i * 32;
#pragma unroll
            for (int j = 0; j < 8; j++) {
                u64 h2 = *(const u64*)(hrow + j * HP);
                acc[j][0] = fma2(h2, w0, acc[j][0]);
                acc[j][1] = fma2(h2, w1, acc[j][1]);
                acc[j][2] = fma2(h2, w2, acc[j][2]);
                acc[j][3] = fma2(h2, w3, acc[j][3]);
                acc[j][4] = fma2(h2, w4, acc[j][4]);
                acc[j][5] = fma2(h2, w5, acc[j][5]);
                acc[j][6] = fma2(h2, w6, acc[j][6]);
                acc[j][7] = fma2(h2, w7, acc[j][7]);
            }
        }

        // --- Split-K reduction in two passes (buf holds one batch-quad half)
        float4 red;
        red.x = red.y = red.z = red.w = 0.f;

        // pass 0: batches j=0..3
#pragma unroll
        for (int j = 0; j < 4; j++) {
            float s[8];
#pragma unroll
            for (int c = 0; c < 8; c++) {
                float lo, hi;
                unpack2(acc[j][c], lo, hi);
                s[c] = lo + hi;
            }
            float* dst = stbase + j * 8;
            float4 v0 = {s[0], s[1], s[2], s[3]};
            float4 v1 = {s[4], s[5], s[6], s[7]};
            *(float4*)dst       = v0;
            *(float4*)(dst + 4) = v1;
        }
        __syncthreads();
        if (pass_sel == 0) {
#pragma unroll
            for (int k2 = 0; k2 < 16; k2++) {
                float4 v = *(const float4*)(redbase + k2 * BUFP);
                red.x += v.x; red.y += v.y; red.z += v.z; red.w += v.w;
            }
        }
        __syncthreads();

        // pass 1: batches j=4..7
#pragma unroll
        for (int j = 4; j < 8; j++) {
            float s[8];
#pragma unroll
            for (int c = 0; c < 8; c++) {
                float lo, hi;
                unpack2(acc[j][c], lo, hi);
                s[c] = lo + hi;
            }
            float* dst = stbase + (j & 3) * 8;
            float4 v0 = {s[0], s[1], s[2], s[3]};
            float4 v1 = {s[4], s[5], s[6], s[7]};
            *(float4*)dst       = v0;
            *(float4*)(dst + 4) = v1;
        }
        __syncthreads();
        if (pass_sel == 1) {
#pragma unroll
            for (int k2 = 0; k2 < 16; k2++) {
                float4 v = *(const float4*)(redbase + k2 * BUFP);
                red.x += v.x; red.y += v.y; red.z += v.z; red.w += v.w;
            }
        }

        // --- Gates + state update (every thread owns one (b, hcol))
        const float gi = red.x + xp_i + bh_i;
        const float gf = red.y + xp_f + bh_f;
        const float go = red.z + xp_o + bh_o;
        const float gz = red.w + xp_z + bh_z;

        const float iv = 1.f / (1.f + __expf(-gi));
        const float fv = 1.f / (1.f + __expf(-gf));
        const float ov = 1.f / (1.f + __expf(-go));
        const float zv = 1.f - 2.f / (__expf(2.f * gz) + 1.f);   // tanh

        c_st = fmaf(iv, zv, fv * c_st);
        const float th = 1.f - 2.f / (__expf(2.f * c_st) + 1.f); // tanh(c)
        const float hv_ = ov * th;

        hsum += hv_;
        csum += c_st;

        g_h[rb ^ 1][fb * HDIM + c0 + fq] = hv_;

        grid_barrier();   // includes __syncthreads: protects buf & h_s reuse
    }

    const float inv = 1.0f / (float)T_STEPS;
    out[fb * HDIM + c0 + fq]                = hsum * inv;
    out[BATCH * HDIM + fb * HDIM + c0 + fq] = csum * inv;
}

// ---------------------------------------------------------------------------
extern "C" void kernel_launch(void* const* d_in, const int* in_sizes, int n_in,
                              void* d_out, int out_size) {
    const float* X  = (const float*)d_in[0];
    const float* Wx = (const float*)d_in[1];
    const float* bx = (const float*)d_in[2];
    const float* Wh = (const float*)d_in[3];
    const float* bh = (const float*)d_in[4];
    float* out = (float*)d_out;

    cudaFuncSetAttribute(lstm_seq, cudaFuncAttributeMaxDynamicSharedMemorySize,
                         SMEM_TOTAL);

    dim3 gemm_grid(2048 / 128, M_ROWS / 128);  // (16, 1024)
    sgemm_xproj<<<gemm_grid, 256>>>(X, Wx, bx);

    lstm_seq<<<NBLK, 256, SMEM_TOTAL>>>(Wh, bh, out);
}

// round 4
// speedup vs baseline: 2.1439x; 1.2312x over previous
#include <cuda_runtime.h>
#include <cuda_bf16.h>
#include <math.h>

// Problem dims
#define T_STEPS 2048
#define BATCH   64
#define DIN     512
#define HDIM    512
#define G4      2048            // 4*H
#define M_ROWS  131072          // T*B
#define NBLK    128

typedef unsigned long long u64;
typedef unsigned int u32;

// Scratch (device globals: allocation-free contract)
__device__ float g_xproj[268435456];            // [T*B][4H] fp32 = 1 GiB
__device__ __nv_bfloat16 g_xhi[67108864];       // X hi  (bf16) 128MB
__device__ __nv_bfloat16 g_xlo[67108864];       // X lo  (bf16) 128MB
__device__ __nv_bfloat16 g_wxthi[1048576];      // Wx^T hi [2048][512]
__device__ __nv_bfloat16 g_wxtlo[1048576];      // Wx^T lo
__device__ float g_h[2][BATCH * HDIM];          // ping-pong hidden state
__device__ unsigned long long g_arrive  = 0ULL;
__device__ unsigned long long g_release = 0ULL;

// ---------------------------------------------------------------------------
// small PTX helpers
// ---------------------------------------------------------------------------
__device__ __forceinline__ u64 pack2(float lo, float hi) {
    u64 r; asm("mov.b64 %0, {%1, %2};" : "=l"(r) : "f"(lo), "f"(hi)); return r;
}
__device__ __forceinline__ void unpack2(u64 v, float& lo, float& hi) {
    asm("mov.b64 {%0, %1}, %2;" : "=f"(lo), "=f"(hi) : "l"(v));
}
__device__ __forceinline__ u64 fma2(u64 a, u64 b, u64 c) {
    u64 d; asm("fma.rn.f32x2 %0, %1, %2, %3;" : "=l"(d) : "l"(a), "l"(b), "l"(c));
    return d;
}
__device__ __forceinline__ u32 smem_u32(const void* p) {
    u32 a;
    asm("{ .reg .u64 t; cvta.to.shared.u64 t, %1; cvt.u32.u64 %0, t; }"
        : "=r"(a) : "l"(p));
    return a;
}
__device__ __forceinline__ void cpa16(u32 dst, const void* src) {
    asm volatile("cp.async.cg.shared.global [%0], [%1], 16;"
                 :: "r"(dst), "l"(src));
}
#define CP_COMMIT() asm volatile("cp.async.commit_group;" ::: "memory")

#define LDSM4(r0, r1, r2, r3, a) \
    asm volatile("ldmatrix.sync.aligned.m8n8.x4.shared.b16 {%0,%1,%2,%3}, [%4];" \
                 : "=r"(r0), "=r"(r1), "=r"(r2), "=r"(r3) : "r"(a))

#define MMA_BF16(c, a, b) \
    asm volatile("mma.sync.aligned.m16n8k16.row.col.f32.bf16.bf16.f32 " \
                 "{%0,%1,%2,%3}, {%4,%5,%6,%7}, {%8,%9}, {%0,%1,%2,%3};" \
                 : "+f"((c)[0]), "+f"((c)[1]), "+f"((c)[2]), "+f"((c)[3]) \
                 : "r"((a)[0]), "r"((a)[1]), "r"((a)[2]), "r"((a)[3]), \
                   "r"((b)[0]), "r"((b)[1]))

// ---------------------------------------------------------------------------
// Conversion kernels: fp32 -> bf16 hi/lo split
// ---------------------------------------------------------------------------
__global__ __launch_bounds__(256) void convert_x(const float* __restrict__ X) {
    size_t i = (size_t)blockIdx.x * 256 + threadIdx.x;   // over 16777216 float4
    float4 v = ((const float4*)X)[i];
    __nv_bfloat16 h0 = __float2bfloat16(v.x);
    __nv_bfloat16 h1 = __float2bfloat16(v.y);
    __nv_bfloat16 h2 = __float2bfloat16(v.z);
    __nv_bfloat16 h3 = __float2bfloat16(v.w);
    __nv_bfloat16 l0 = __float2bfloat16(v.x - __bfloat162float(h0));
    __nv_bfloat16 l1 = __float2bfloat16(v.y - __bfloat162float(h1));
    __nv_bfloat16 l2 = __float2bfloat16(v.z - __bfloat162float(h2));
    __nv_bfloat16 l3 = __float2bfloat16(v.w - __bfloat162float(h3));
    __nv_bfloat162* ph = (__nv_bfloat162*)g_xhi;
    __nv_bfloat162* pl = (__nv_bfloat162*)g_xlo;
    ph[i * 2]     = __nv_bfloat162(h0, h1);
    ph[i * 2 + 1] = __nv_bfloat162(h2, h3);
    pl[i * 2]     = __nv_bfloat162(l0, l1);
    pl[i * 2 + 1] = __nv_bfloat162(l2, l3);
}

__global__ __launch_bounds__(256) void convert_w(const float* __restrict__ Wx) {
    int idx = blockIdx.x * 256 + threadIdx.x;    // 1048576
    int k = idx >> 11, g = idx & 2047;
    float v = Wx[idx];
    __nv_bfloat16 h = __float2bfloat16(v);
    __nv_bfloat16 l = __float2bfloat16(v - __bfloat162float(h));
    g_wxthi[(size_t)g * 512 + k] = h;
    g_wxtlo[(size_t)g * 512 + k] = l;
}

// ---------------------------------------------------------------------------
// Kernel 1: x_proj = X @ Wx + bx via mma.sync bf16 (sm_80 ISA — works on the
// plain sm_103 lowering this build uses; tcgen05 does NOT).
// 3-term compensation as one K-concatenated GEMM:
//   A' = [Xhi | Xhi | Xlo], B' = [Whi | Wlo | Whi], K' = 1536.
// CTA tile 128x128, BK=32, cp.async double-buffered, padded smem (pitch 80B,
// conflict-free ldmatrix). 8 warps = 4(m) x 2(n), warp tile 32x64.
// ---------------------------------------------------------------------------
#define TILE_B   10240          // 128 rows * 80 bytes
#define STAGE_B  (2 * TILE_B)   // A + B per stage

__device__ __forceinline__ void load_tile(
    u32 sA, u32 sB,
    const __nv_bfloat16* __restrict__ asrc,   // + m0*512 already applied
    const __nv_bfloat16* __restrict__ bsrc,   // + bn*512 already applied
    int kc, int tid)
{
#pragma unroll
    for (int p = 0; p < 2; p++) {
        int idx = tid + p * 256;
        int row = idx >> 2, seg = idx & 3;
        cpa16(sA + row * 80 + seg * 16,
              (const char*)(asrc + (size_t)row * 512 + kc) + seg * 16);
    }
#pragma unroll
    for (int p = 0; p < 2; p++) {
        int idx = tid + p * 256;
        int row = idx >> 2, seg = idx & 3;
        cpa16(sB + row * 80 + seg * 16,
              (const char*)(bsrc + (size_t)row * 512 + kc) + seg * 16);
    }
}

__global__ __launch_bounds__(256, 2) void gemm_xproj_hmma(
    const float* __restrict__ bias)
{
    __shared__ char smem[2 * STAGE_B];   // 40960 B
    u32 sb = smem_u32(smem);

    const int tid  = threadIdx.x;
    const int lane = tid & 31;
    const int wid  = tid >> 5;
    const int m0w  = (wid & 3) * 32;     // warp m offset in tile
    const int n0w  = (wid >> 2) * 64;    // warp n offset in tile

    const int bn = blockIdx.x * 128;
    const int m0 = blockIdx.y * 128;

    const __nv_bfloat16* a_hi = g_xhi + (size_t)m0 * 512;
    const __nv_bfloat16* a_lo = g_xlo + (size_t)m0 * 512;
    const __nv_bfloat16* b_hi = g_wxthi + (size_t)bn * 512;
    const __nv_bfloat16* b_lo = g_wxtlo + (size_t)bn * 512;

    float acc[2][8][4];
#pragma unroll
    for (int mt = 0; mt < 2; mt++)
#pragma unroll
        for (int nt = 0; nt < 8; nt++)
#pragma unroll
            for (int r = 0; r < 4; r++) acc[mt][nt][r] = 0.f;

    // chunk c in [0,48): segment s = c>>4 selects (A,B) pair; kc = (c&15)*32
    // s=0: (hi,hi)  s=1: (hi,lo)  s=2: (lo,hi)
    load_tile(sb, sb + TILE_B, a_hi, b_hi, 0, tid);
    CP_COMMIT();

#pragma unroll 1
    for (int c = 0; c < 48; c++) {
        const int st = c & 1;
        if (c + 1 < 48) {
            const int cn = c + 1;
            const int s  = cn >> 4;
            const int kc = (cn & 15) * 32;
            const __nv_bfloat16* as = (s == 2) ? a_lo : a_hi;
            const __nv_bfloat16* bs = (s == 1) ? b_lo : b_hi;
            u32 base = sb + (u32)(st ^ 1) * STAGE_B;
            load_tile(base, base + TILE_B, as, bs, kc, tid);
            CP_COMMIT();
            asm volatile("cp.async.wait_group 1;" ::: "memory");
        } else {
            asm volatile("cp.async.wait_group 0;" ::: "memory");
        }
        __syncthreads();

        const u32 sA = sb + (u32)st * STAGE_B;
        const u32 sB = sA + TILE_B;

#pragma unroll
        for (int k16 = 0; k16 < 2; k16++) {
            const int kb = k16 * 16;   // bf16 col offset
            u32 a_frag[2][4];
#pragma unroll
            for (int mt = 0; mt < 2; mt++) {
                u32 addr = sA + (u32)((m0w + mt * 16 + (lane & 15)) * 40
                                      + kb + (lane >> 4) * 8) * 2;
                LDSM4(a_frag[mt][0], a_frag[mt][1], a_frag[mt][2], a_frag[mt][3], addr);
            }
            u32 b_frag[8][2];
#pragma unroll
            for (int ntp = 0; ntp < 4; ntp++) {
                u32 addr = sB + (u32)((n0w + ntp * 16 + (lane & 15)) * 40
                                      + kb + (lane >> 4) * 8) * 2;
                u32 r0, r1, r2, r3;
                LDSM4(r0, r1, r2, r3, addr);
                b_frag[2 * ntp][0]     = r0;  // n-tile 2*ntp   : b0
                b_frag[2 * ntp][1]     = r2;  //                : b1
                b_frag[2 * ntp + 1][0] = r1;  // n-tile 2*ntp+1 : b0
                b_frag[2 * ntp + 1][1] = r3;  //                : b1
            }
#pragma unroll
            for (int mt = 0; mt < 2; mt++)
#pragma unroll
                for (int nt = 0; nt < 8; nt++)
                    MMA_BF16(acc[mt][nt], a_frag[mt], b_frag[nt]);
        }
        __syncthreads();   // protect stage before next prefetch overwrites it
    }

    // Epilogue: add bias, store fp32
    const int mrow  = m0 + m0w + (lane >> 2);
    const int ncol0 = bn + n0w + (lane & 3) * 2;
#pragma unroll
    for (int mt = 0; mt < 2; mt++) {
#pragma unroll
        for (int nt = 0; nt < 8; nt++) {
            const int col = ncol0 + nt * 8;
            const float2 bs = __ldg((const float2*)(bias + col));
            const int r0 = mrow + mt * 16;
            float2 v0, v1;
            v0.x = acc[mt][nt][0] + bs.x; v0.y = acc[mt][nt][1] + bs.y;
            v1.x = acc[mt][nt][2] + bs.x; v1.y = acc[mt][nt][3] + bs.y;
            *(float2*)(g_xproj + (size_t)r0 * 2048 + col)       = v0;
            *(float2*)(g_xproj + (size_t)(r0 + 8) * 2048 + col) = v1;
        }
    }
}

// ---------------------------------------------------------------------------
// Kernel 2: persistent sequential recurrence. 128 CTAs x 256 threads.
// f32x2 register tiling; split-K reduction overlaid on h_s (dead between
// syncs), single pass, conflict-free layouts (verified).
// ---------------------------------------------------------------------------
#define HP 516    // h_s row pitch (floats)
#define WPU 18    // wpair row pitch (in u64)
#define SLICE 516 // reduction slice stride (floats) per (gp,ks) unit

#define SMEM_H_BYTES (BATCH * HP * 4)    // 132096
#define SMEM_W_BYTES (256 * WPU * 8)     // 36864
#define SMEM_TOTAL (SMEM_H_BYTES + SMEM_W_BYTES)

__device__ __forceinline__ void grid_barrier() {
    __syncthreads();
    if (threadIdx.x == 0) {
        __threadfence();
        unsigned long long t = atomicAdd(&g_arrive, 1ULL) + 1ULL;
        unsigned long long n = (unsigned long long)NBLK;
        unsigned long long target = ((t + n - 1ULL) / n) * n;
        if (t == target) {
            atomicMax(&g_release, target);
        } else {
            unsigned long long r;
            do {
                asm volatile("ld.volatile.global.u64 %0, [%1];"
                             : "=l"(r) : "l"(&g_release));
            } while (r < target);
        }
        __threadfence();
    }
    __syncthreads();
}

__global__ __launch_bounds__(256, 1) void lstm_seq(
    const float* __restrict__ Wh,   // [512][2048]
    const float* __restrict__ bh,   // [2048]
    float* __restrict__ out)        // [2][64][512]
{
    extern __shared__ char smem[];
    float* h_s = (float*)smem;
    u64*   wp  = (u64*)(smem + SMEM_H_BYTES);
    float* buf = h_s;                 // overlay: dead between syncs

    const int tid = threadIdx.x;
    const int cta = blockIdx.x;
    const int c0  = cta * 4;

    const int ks = tid & 15;
    const int gp = (tid >> 4) & 1;
    const int bg = tid >> 5;
    const int u  = gp * 16 + ks;     // reduction slice id 0..31

    const int fb = tid >> 2;         // 0..63
    const int fq = tid & 3;          // 0..3
    const int gpf = fq >> 1;

    // Paired Wh: wp[kk*WPU + c] = (Wh[2kk][col], Wh[2kk+1][col]), c = q*4+g
    for (int idx = tid; idx < 256 * 16; idx += 256) {
        int kk = idx >> 4, c = idx & 15;
        int q = c >> 2, g = c & 3;
        int col = g * HDIM + c0 + q;
        float lo = Wh[(size_t)(2 * kk) * G4 + col];
        float hi = Wh[(size_t)(2 * kk + 1) * G4 + col];
        wp[kk * WPU + c] = pack2(lo, hi);
    }

    const float bh_i = bh[0 * HDIM + c0 + fq];
    const float bh_f = bh[1 * HDIM + c0 + fq];
    const float bh_o = bh[2 * HDIM + c0 + fq];
    const float bh_z = bh[3 * HDIM + c0 + fq];

    g_h[0][cta * 256 + tid] = 0.f;

    grid_barrier();

    float c_st = 0.f, hsum = 0.f, csum = 0.f;

    const float* hbase  = h_s + bg * 8 * HP + 2 * ks;
    const u64*   wbase  = wp + ks * WPU + gp * 8;
    float*       stbase = buf + u * SLICE + bg * 64;
    const float* redbase = buf + gpf * (16 * SLICE) + fb * 8 + (fq & 1) * 4;

    for (int t = 0; t < T_STEPS; t++) {
        const int rb = t & 1;

        const float* xr = g_xproj + (size_t)t * (BATCH * G4)
                        + (size_t)fb * G4 + c0 + fq;
        const float xp_i = xr[0];
        const float xp_f = xr[HDIM];
        const float xp_o = xr[2 * HDIM];
        const float xp_z = xr[3 * HDIM];

        // Broadcast h_{t-1} into smem
        const float4* hg = (const float4*)g_h[rb];
#pragma unroll
        for (int v = tid; v < (BATCH * HDIM) / 4; v += 256) {
            float4 hv = hg[v];
            int bb = v >> 7;
            int cc = (v & 127) << 2;
            *(float4*)&h_s[bb * HP + cc] = hv;
        }
        __syncthreads();

        // GEMM slice: 8 batches x 8 gate-cols, f32x2 pairs, split-K 16
        u64 acc[8][8];
#pragma unroll
        for (int j = 0; j < 8; j++)
#pragma unroll
            for (int c = 0; c < 8; c++) acc[j][c] = 0ULL;

#pragma unroll 2
        for (int i = 0; i < 16; i++) {
            const u64* wr = wbase + i * 16 * WPU;
            ulonglong2 p0 = *(const ulonglong2*)(wr + 0);
            ulonglong2 p1 = *(const ulonglong2*)(wr + 2);
            ulonglong2 p2 = *(const ulonglong2*)(wr + 4);
            ulonglong2 p3 = *(const ulonglong2*)(wr + 6);
            u64 w0 = p0.x, w1 = p0.y, w2 = p1.x, w3 = p1.y;
            u64 w4 = p2.x, w5 = p2.y, w6 = p3.x, w7 = p3.y;
            const float* hrow = hbase + i * 32;
#pragma unroll
            for (int j = 0; j < 8; j++) {
                u64 h2 = *(const u64*)(hrow + j * HP);
                acc[j][0] = fma2(h2, w0, acc[j][0]);
                acc[j][1] = fma2(h2, w1, acc[j][1]);
                acc[j][2] = fma2(h2, w2, acc[j][2]);
                acc[j][3] = fma2(h2, w3, acc[j][3]);
                acc[j][4] = fma2(h2, w4, acc[j][4]);
                acc[j][5] = fma2(h2, w5, acc[j][5]);
                acc[j][6] = fma2(h2, w6, acc[j][6]);
                acc[j][7] = fma2(h2, w7, acc[j][7]);
            }
        }

        // Single-pass split-K reduction overlaid on h_s
        __syncthreads();   // all h_s reads done before overwriting
#pragma unroll
        for (int j = 0; j < 8; j++) {
            float s[8];
#pragma unroll
            for (int c = 0; c < 8; c++) {
                float lo, hi;
                unpack2(acc[j][c], lo, hi);
                s[c] = lo + hi;
            }
            float* dst = stbase + j * 8;
            float4 v0 = {s[0], s[1], s[2], s[3]};
            float4 v1 = {s[4], s[5], s[6], s[7]};
            *(float4*)dst       = v0;
            *(float4*)(dst + 4) = v1;
        }
        __syncthreads();

        float4 red;
        red.x = red.y = red.z = red.w = 0.f;
#pragma unroll
        for (int k2 = 0; k2 < 16; k2++) {
            float4 v = *(const float4*)(redbase + k2 * SLICE);
            red.x += v.x; red.y += v.y; red.z += v.z; red.w += v.w;
        }

        const float gi = red.x + xp_i + bh_i;
        const float gf = red.y + xp_f + bh_f;
        const float go = red.z + xp_o + bh_o;
        const float gz = red.w + xp_z + bh_z;

        const float iv = 1.f / (1.f + __expf(-gi));
        const float fv = 1.f / (1.f + __expf(-gf));
        const float ov = 1.f / (1.f + __expf(-go));
        const float zv = 1.f - 2.f / (__expf(2.f * gz) + 1.f);

        c_st = fmaf(iv, zv, fv * c_st);
        const float th = 1.f - 2.f / (__expf(2.f * c_st) + 1.f);
        const float hv_ = ov * th;

        hsum += hv_;
        csum += c_st;

        g_h[rb ^ 1][fb * HDIM + c0 + fq] = hv_;

        grid_barrier();
    }

    const float inv = 1.0f / (float)T_STEPS;
    out[fb * HDIM + c0 + fq]                = hsum * inv;
    out[BATCH * HDIM + fb * HDIM + c0 + fq] = csum * inv;
}

// ---------------------------------------------------------------------------
extern "C" void kernel_launch(void* const* d_in, const int* in_sizes, int n_in,
                              void* d_out, int out_size) {
    const float* X  = (const float*)d_in[0];
    const float* Wx = (const float*)d_in[1];
    const float* bx = (const float*)d_in[2];
    const float* Wh = (const float*)d_in[3];
    const float* bh = (const float*)d_in[4];
    float* out = (float*)d_out;

    cudaFuncSetAttribute(lstm_seq,
                         cudaFuncAttributeMaxDynamicSharedMemorySize, SMEM_TOTAL);

    convert_x<<<65536, 256>>>(X);
    convert_w<<<4096, 256>>>(Wx);

    dim3 gemm_grid(16, 1024);   // N tiles x M tiles
    gemm_xproj_hmma<<<gemm_grid, 256>>>(bx);

    lstm_seq<<<NBLK, 256, SMEM_TOTAL>>>(Wh, bh, out);
}

// round 5
// speedup vs baseline: 2.4263x; 1.1317x over previous
#include <cuda_runtime.h>
#include <cuda_bf16.h>
#include <math.h>

// Problem dims
#define T_STEPS 2048
#define BATCH   64
#define DIN     512
#define HDIM    512
#define G4      2048            // 4*H
#define M_ROWS  131072          // T*B
#define NBLK    128

typedef unsigned long long u64;
typedef unsigned int u32;

// Scratch (device globals: allocation-free contract)
// g_xproj layout: [t][cta(128)][batch(64)][q(4)][g(4)] fp32  (131072 floats / t)
__device__ float g_xproj[268435456];            // 1 GiB
__device__ __nv_bfloat16 g_xhi[67108864];       // X hi  (bf16)
__device__ __nv_bfloat16 g_xlo[67108864];       // X lo  (bf16)
__device__ __nv_bfloat16 g_wxthi[1048576];      // Wx^T hi [2048][512]
__device__ __nv_bfloat16 g_wxtlo[1048576];      // Wx^T lo
__device__ __nv_bfloat16 g_hb[2][2][32768];     // h state [buf][hi/lo][b*512+col]
__device__ unsigned long long g_arrive  = 0ULL;
__device__ unsigned long long g_release = 0ULL;

// ---------------------------------------------------------------------------
// PTX helpers
// ---------------------------------------------------------------------------
__device__ __forceinline__ u32 smem_u32(const void* p) {
    u32 a;
    asm("{ .reg .u64 t; cvta.to.shared.u64 t, %1; cvt.u32.u64 %0, t; }"
        : "=r"(a) : "l"(p));
    return a;
}
__device__ __forceinline__ void cpa16(u32 dst, const void* src) {
    asm volatile("cp.async.cg.shared.global [%0], [%1], 16;"
                 :: "r"(dst), "l"(src));
}
#define CP_COMMIT() asm volatile("cp.async.commit_group;" ::: "memory")

#define LDSM4(r0, r1, r2, r3, a) \
    asm volatile("ldmatrix.sync.aligned.m8n8.x4.shared.b16 {%0,%1,%2,%3}, [%4];" \
                 : "=r"(r0), "=r"(r1), "=r"(r2), "=r"(r3) : "r"(a))
#define LDSM2(r0, r1, a) \
    asm volatile("ldmatrix.sync.aligned.m8n8.x2.shared.b16 {%0,%1}, [%2];" \
                 : "=r"(r0), "=r"(r1) : "r"(a))

#define MMA_BF16(c, a, b) \
    asm volatile("mma.sync.aligned.m16n8k16.row.col.f32.bf16.bf16.f32 " \
                 "{%0,%1,%2,%3}, {%4,%5,%6,%7}, {%8,%9}, {%0,%1,%2,%3};" \
                 : "+f"((c)[0]), "+f"((c)[1]), "+f"((c)[2]), "+f"((c)[3]) \
                 : "r"((a)[0]), "r"((a)[1]), "r"((a)[2]), "r"((a)[3]), \
                   "r"((b)[0]), "r"((b)[1]))

// ---------------------------------------------------------------------------
// Conversion kernels: fp32 -> bf16 hi/lo split
// ---------------------------------------------------------------------------
__global__ __launch_bounds__(256) void convert_x(const float* __restrict__ X) {
    size_t i = (size_t)blockIdx.x * 256 + threadIdx.x;   // over 16777216 float4
    float4 v = ((const float4*)X)[i];
    __nv_bfloat16 h0 = __float2bfloat16(v.x);
    __nv_bfloat16 h1 = __float2bfloat16(v.y);
    __nv_bfloat16 h2 = __float2bfloat16(v.z);
    __nv_bfloat16 h3 = __float2bfloat16(v.w);
    __nv_bfloat16 l0 = __float2bfloat16(v.x - __bfloat162float(h0));
    __nv_bfloat16 l1 = __float2bfloat16(v.y - __bfloat162float(h1));
    __nv_bfloat16 l2 = __float2bfloat16(v.z - __bfloat162float(h2));
    __nv_bfloat16 l3 = __float2bfloat16(v.w - __bfloat162float(h3));
    __nv_bfloat162* ph = (__nv_bfloat162*)g_xhi;
    __nv_bfloat162* pl = (__nv_bfloat162*)g_xlo;
    ph[i * 2]     = __nv_bfloat162(h0, h1);
    ph[i * 2 + 1] = __nv_bfloat162(h2, h3);
    pl[i * 2]     = __nv_bfloat162(l0, l1);
    pl[i * 2 + 1] = __nv_bfloat162(l2, l3);
}

__global__ __launch_bounds__(256) void convert_w(const float* __restrict__ Wx) {
    int idx = blockIdx.x * 256 + threadIdx.x;    // 1048576
    int k = idx >> 11, g = idx & 2047;
    float v = Wx[idx];
    __nv_bfloat16 h = __float2bfloat16(v);
    __nv_bfloat16 l = __float2bfloat16(v - __bfloat162float(h));
    g_wxthi[(size_t)g * 512 + k] = h;
    g_wxtlo[(size_t)g * 512 + k] = l;
}

// ---------------------------------------------------------------------------
// Kernel 1: x_proj = X @ Wx + bx via mma.sync bf16, 3-term compensation.
// Epilogue writes the PERMUTED layout [t][cta][batch][q][g].
// ---------------------------------------------------------------------------
#define TILE_B   10240          // 128 rows * 80 bytes
#define STAGE_B  (2 * TILE_B)   // A + B per stage

__device__ __forceinline__ void load_tile(
    u32 sA, u32 sB,
    const __nv_bfloat16* __restrict__ asrc,
    const __nv_bfloat16* __restrict__ bsrc,
    int kc, int tid)
{
#pragma unroll
    for (int p = 0; p < 2; p++) {
        int idx = tid + p * 256;
        int row = idx >> 2, seg = idx & 3;
        cpa16(sA + row * 80 + seg * 16,
              (const char*)(asrc + (size_t)row * 512 + kc) + seg * 16);
    }
#pragma unroll
    for (int p = 0; p < 2; p++) {
        int idx = tid + p * 256;
        int row = idx >> 2, seg = idx & 3;
        cpa16(sB + row * 80 + seg * 16,
              (const char*)(bsrc + (size_t)row * 512 + kc) + seg * 16);
    }
}

__global__ __launch_bounds__(256, 2) void gemm_xproj_hmma(
    const float* __restrict__ bias)
{
    __shared__ char smem[2 * STAGE_B];
    u32 sb = smem_u32(smem);

    const int tid  = threadIdx.x;
    const int lane = tid & 31;
    const int wid  = tid >> 5;
    const int m0w  = (wid & 3) * 32;
    const int n0w  = (wid >> 2) * 64;

    const int bn = blockIdx.x * 128;
    const int m0 = blockIdx.y * 128;

    const __nv_bfloat16* a_hi = g_xhi + (size_t)m0 * 512;
    const __nv_bfloat16* a_lo = g_xlo + (size_t)m0 * 512;
    const __nv_bfloat16* b_hi = g_wxthi + (size_t)bn * 512;
    const __nv_bfloat16* b_lo = g_wxtlo + (size_t)bn * 512;

    float acc[2][8][4];
#pragma unroll
    for (int mt = 0; mt < 2; mt++)
#pragma unroll
        for (int nt = 0; nt < 8; nt++)
#pragma unroll
            for (int r = 0; r < 4; r++) acc[mt][nt][r] = 0.f;

    load_tile(sb, sb + TILE_B, a_hi, b_hi, 0, tid);
    CP_COMMIT();

#pragma unroll 1
    for (int c = 0; c < 48; c++) {
        const int st = c & 1;
        if (c + 1 < 48) {
            const int cn = c + 1;
            const int s  = cn >> 4;
            const int kc = (cn & 15) * 32;
            const __nv_bfloat16* as = (s == 2) ? a_lo : a_hi;
            const __nv_bfloat16* bs = (s == 1) ? b_lo : b_hi;
            u32 base = sb + (u32)(st ^ 1) * STAGE_B;
            load_tile(base, base + TILE_B, as, bs, kc, tid);
            CP_COMMIT();
            asm volatile("cp.async.wait_group 1;" ::: "memory");
        } else {
            asm volatile("cp.async.wait_group 0;" ::: "memory");
        }
        __syncthreads();

        const u32 sA = sb + (u32)st * STAGE_B;
        const u32 sB = sA + TILE_B;

#pragma unroll
        for (int k16 = 0; k16 < 2; k16++) {
            const int kb = k16 * 16;
            u32 a_frag[2][4];
#pragma unroll
            for (int mt = 0; mt < 2; mt++) {
                u32 addr = sA + (u32)((m0w + mt * 16 + (lane & 15)) * 40
                                      + kb + (lane >> 4) * 8) * 2;
                LDSM4(a_frag[mt][0], a_frag[mt][1], a_frag[mt][2], a_frag[mt][3], addr);
            }
            u32 b_frag[8][2];
#pragma unroll
            for (int ntp = 0; ntp < 4; ntp++) {
                u32 addr = sB + (u32)((n0w + ntp * 16 + (lane & 15)) * 40
                                      + kb + (lane >> 4) * 8) * 2;
                u32 r0, r1, r2, r3;
                LDSM4(r0, r1, r2, r3, addr);
                b_frag[2 * ntp][0]     = r0;
                b_frag[2 * ntp][1]     = r2;
                b_frag[2 * ntp + 1][0] = r1;
                b_frag[2 * ntp + 1][1] = r3;
            }
#pragma unroll
            for (int mt = 0; mt < 2; mt++)
#pragma unroll
                for (int nt = 0; nt < 8; nt++)
                    MMA_BF16(acc[mt][nt], a_frag[mt], b_frag[nt]);
        }
        __syncthreads();
    }

    // Epilogue: bias + permuted store [t][cta][batch][q][g]
    const int mrow  = m0 + m0w + (lane >> 2);
    const int ncol0 = bn + n0w + (lane & 3) * 2;
#pragma unroll
    for (int mt = 0; mt < 2; mt++) {
#pragma unroll
        for (int nt = 0; nt < 8; nt++) {
            const int col = ncol0 + nt * 8;       // even
            const float2 bs = __ldg((const float2*)(bias + col));
            const int g = col >> 9;
            const int hcol = col & 511;
            const size_t cb = (size_t)(hcol >> 2) * 1024 + (hcol & 3) * 4 + g;
            const int rA = mrow + mt * 16;
            const int rB = rA + 8;
            const size_t baseA = (size_t)(rA >> 6) * 131072 + (rA & 63) * 16;
            const size_t baseB = (size_t)(rB >> 6) * 131072 + (rB & 63) * 16;
            g_xproj[baseA + cb]     = acc[mt][nt][0] + bs.x;
            g_xproj[baseA + cb + 4] = acc[mt][nt][1] + bs.y;
            g_xproj[baseB + cb]     = acc[mt][nt][2] + bs.x;
            g_xproj[baseB + cb + 4] = acc[mt][nt][3] + bs.y;
        }
    }
}

// ---------------------------------------------------------------------------
// Kernel 2: persistent recurrence, HMMA inner GEMM.
// 128 CTAs x 256 threads. CTA owns h-cols [4*cta, 4*cta+4) -> 16 gate-cols
// ordered n = q*4 + g. Warp w: m-tile (w&3)*16, n-half (w>>2)*8 -> one
// m16n8 fragment, 3-term bf16 compensation, acc[4] registers.
// ---------------------------------------------------------------------------
#define APB 1040          // plane row pitch bytes (520 bf16: conflict-free LDSM)
#define SM_AHI 0
#define SM_ALO 66560
#define SM_BHI 133120
#define SM_BLO 149760
#define SM_TOTAL 166400

__device__ __forceinline__ void grid_barrier() {
    __syncthreads();
    if (threadIdx.x == 0) {
        __threadfence();
        unsigned long long t = atomicAdd(&g_arrive, 1ULL) + 1ULL;
        unsigned long long n = (unsigned long long)NBLK;
        unsigned long long target = ((t + n - 1ULL) / n) * n;
        if (t == target) {
            atomicMax(&g_release, target);
        } else {
            unsigned long long r;
            do {
                asm volatile("ld.volatile.global.u64 %0, [%1];"
                             : "=l"(r) : "l"(&g_release));
            } while (r < target);
        }
        __threadfence();
    }
    __syncthreads();
}

__global__ __launch_bounds__(256, 1) void lstm_seq(
    const float* __restrict__ Wh,   // [512][2048]
    const float* __restrict__ bh,   // [2048]
    float* __restrict__ out)        // [2][64][512]
{
    extern __shared__ char smem[];
    u32 sb = smem_u32(smem);

    const int tid  = threadIdx.x;
    const int cta  = blockIdx.x;
    const int c0   = cta * 4;
    const int lane = tid & 31;
    const int wid  = tid >> 5;
    const int m0w  = (wid & 3) * 16;
    const int nq   = wid >> 2;           // 0/1: gate-col octet

    // --- Load Wh slice into B planes (hi/lo), n = q*4+g, k-contiguous rows
    for (int idx = tid; idx < 16 * 512; idx += 256) {
        int n = idx & 15, k = idx >> 4;
        int q = n >> 2, g = n & 3;
        float v = Wh[(size_t)k * G4 + g * HDIM + c0 + q];
        __nv_bfloat16 h = __float2bfloat16(v);
        __nv_bfloat16 l = __float2bfloat16(v - __bfloat162float(h));
        *(__nv_bfloat16*)(smem + SM_BHI + n * APB + k * 2) = h;
        *(__nv_bfloat16*)(smem + SM_BLO + n * APB + k * 2) = l;
    }

    // --- Per-lane identity: 2 states (b0,q) and (b1,q)
    const int q   = nq * 2 + ((lane & 3) >> 1);
    const int col = c0 + q;
    const int r0  = lane >> 2;
    const int b0  = m0w + r0;
    const int b1  = b0 + 8;

    float4 bhv;
    bhv.x = bh[0 * HDIM + col];
    bhv.y = bh[1 * HDIM + col];
    bhv.z = bh[2 * HDIM + col];
    bhv.w = bh[3 * HDIM + col];

    // Zero h buffer 0 (both planes = 32768 u32 total; 32768 threads chip-wide)
    ((u32*)g_hb[0])[cta * 256 + tid] = 0u;

    grid_barrier();

    float cst0 = 0.f, cst1 = 0.f;
    float hs0 = 0.f, hs1 = 0.f, cs0 = 0.f, cs1 = 0.f;

    const u32 a_hi_row = sb + SM_AHI + (u32)(m0w + (lane & 15)) * APB;
    const u32 a_lo_row = sb + SM_ALO + (u32)(m0w + (lane & 15)) * APB;
    const u32 b_hi_row = sb + SM_BHI + (u32)(nq * 8 + (lane & 7)) * APB;
    const u32 b_lo_row = sb + SM_BLO + (u32)(nq * 8 + (lane & 7)) * APB;
    const u32 a_koff = ((u32)(lane >> 4)) * 16;        // bytes
    const u32 b_koff = ((u32)((lane >> 3) & 1)) * 16;  // bytes

    for (int t = 0; t < T_STEPS; t++) {
        const int rb = t & 1;
        const __nv_bfloat16* src_hi = g_hb[rb][0];
        const __nv_bfloat16* src_lo = g_hb[rb][1];

        // Broadcast h planes via cp.async, 2 pipelined k-chunks of 256
#pragma unroll
        for (int c2 = 0; c2 < 2; c2++) {
#pragma unroll
            for (int i = 0; i < 8; i++) {
                int u = tid + i * 256;
                int row = u >> 5, seg = u & 31;
                u32 o = (u32)row * APB + (u32)c2 * 512 + (u32)seg * 16;
                size_t sgo = (size_t)row * 1024 + c2 * 512 + seg * 16;
                cpa16(sb + SM_AHI + o, (const char*)src_hi + sgo);
                cpa16(sb + SM_ALO + o, (const char*)src_lo + sgo);
            }
            CP_COMMIT();
        }

        // x_proj gates for this lane's 2 states (coalesced float4)
        const float* xb = g_xproj + (size_t)t * 131072 + cta * 1024
                        + b0 * 16 + q * 4;
        const float4 x0 = *(const float4*)xb;
        const float4 x1 = *(const float4*)(xb + 128);   // b1 = b0 + 8

        float acc[4] = {0.f, 0.f, 0.f, 0.f};

#pragma unroll
        for (int c2 = 0; c2 < 2; c2++) {
            if (c2 == 0)
                asm volatile("cp.async.wait_group 1;" ::: "memory");
            else
                asm volatile("cp.async.wait_group 0;" ::: "memory");
            __syncthreads();
#pragma unroll
            for (int kk = 0; kk < 16; kk++) {
                const u32 kb = (u32)(c2 * 16 + kk) * 32;   // bytes per k16
                u32 ah[4], al[4], bhf[2], blf[2];
                LDSM4(ah[0], ah[1], ah[2], ah[3], a_hi_row + kb + a_koff);
                LDSM4(al[0], al[1], al[2], al[3], a_lo_row + kb + a_koff);
                LDSM2(bhf[0], bhf[1], b_hi_row + kb + b_koff);
                LDSM2(blf[0], blf[1], b_lo_row + kb + b_koff);
                MMA_BF16(acc, ah, bhf);
                MMA_BF16(acc, ah, blf);
                MMA_BF16(acc, al, bhf);
            }
        }

        // Pair-exchange: lane^1 holds the other two gates of the same (b,q)
        const float p0 = __shfl_xor_sync(0xffffffffu, acc[0], 1);
        const float p1 = __shfl_xor_sync(0xffffffffu, acc[1], 1);
        const float p2 = __shfl_xor_sync(0xffffffffu, acc[2], 1);
        const float p3 = __shfl_xor_sync(0xffffffffu, acc[3], 1);

        float gi0, gf0, go0, gz0, gi1, gf1, go1, gz1;
        if ((lane & 1) == 0) {
            gi0 = acc[0]; gf0 = acc[1]; go0 = p0; gz0 = p1;
            gi1 = acc[2]; gf1 = acc[3]; go1 = p2; gz1 = p3;
        } else {
            gi0 = p0; gf0 = p1; go0 = acc[0]; gz0 = acc[1];
            gi1 = p2; gf1 = p3; go1 = acc[2]; gz1 = acc[3];
        }

        gi0 += x0.x + bhv.x; gf0 += x0.y + bhv.y;
        go0 += x0.z + bhv.z; gz0 += x0.w + bhv.w;
        gi1 += x1.x + bhv.x; gf1 += x1.y + bhv.y;
        go1 += x1.z + bhv.z; gz1 += x1.w + bhv.w;

        const float iv0 = 1.f / (1.f + __expf(-gi0));
        const float fv0 = 1.f / (1.f + __expf(-gf0));
        const float ov0 = 1.f / (1.f + __expf(-go0));
        const float zv0 = 1.f - 2.f / (__expf(2.f * gz0) + 1.f);
        cst0 = fmaf(iv0, zv0, fv0 * cst0);
        const float h0 = ov0 * (1.f - 2.f / (__expf(2.f * cst0) + 1.f));

        const float iv1 = 1.f / (1.f + __expf(-gi1));
        const float fv1 = 1.f / (1.f + __expf(-gf1));
        const float ov1 = 1.f / (1.f + __expf(-go1));
        const float zv1 = 1.f - 2.f / (__expf(2.f * gz1) + 1.f);
        cst1 = fmaf(iv1, zv1, fv1 * cst1);
        const float h1 = ov1 * (1.f - 2.f / (__expf(2.f * cst1) + 1.f));

        hs0 += h0; cs0 += cst0;
        hs1 += h1; cs1 += cst1;

        if ((lane & 1) == 0) {
            const int nb = rb ^ 1;
            __nv_bfloat16 hh0 = __float2bfloat16(h0);
            __nv_bfloat16 hl0 = __float2bfloat16(h0 - __bfloat162float(hh0));
            __nv_bfloat16 hh1 = __float2bfloat16(h1);
            __nv_bfloat16 hl1 = __float2bfloat16(h1 - __bfloat162float(hh1));
            g_hb[nb][0][b0 * HDIM + col] = hh0;
            g_hb[nb][1][b0 * HDIM + col] = hl0;
            g_hb[nb][0][b1 * HDIM + col] = hh1;
            g_hb[nb][1][b1 * HDIM + col] = hl1;
        }

        grid_barrier();
    }

    if ((lane & 1) == 0) {
        const float inv = 1.0f / (float)T_STEPS;
        out[b0 * HDIM + col]                      = hs0 * inv;
        out[BATCH * HDIM + b0 * HDIM + col]       = cs0 * inv;
        out[b1 * HDIM + col]                      = hs1 * inv;
        out[BATCH * HDIM + b1 * HDIM + col]       = cs1 * inv;
    }
}

// ---------------------------------------------------------------------------
extern "C" void kernel_launch(void* const* d_in, const int* in_sizes, int n_in,
                              void* d_out, int out_size) {
    const float* X  = (const float*)d_in[0];
    const float* Wx = (const float*)d_in[1];
    const float* bx = (const float*)d_in[2];
    const float* Wh = (const float*)d_in[3];
    const float* bh = (const float*)d_in[4];
    float* out = (float*)d_out;

    cudaFuncSetAttribute(lstm_seq,
                         cudaFuncAttributeMaxDynamicSharedMemorySize, SM_TOTAL);

    convert_x<<<65536, 256>>>(X);
    convert_w<<<4096, 256>>>(Wx);

    dim3 gemm_grid(16, 1024);
    gemm_xproj_hmma<<<gemm_grid, 256>>>(bx);

    lstm_seq<<<NBLK, 256, SM_TOTAL>>>(Wh, bh, out);
}

// round 6
// speedup vs baseline: 3.0778x; 1.2685x over previous
#include <cuda_runtime.h>
#include <cuda_bf16.h>
#include <cuda_fp16.h>
#include <math.h>

// Problem dims
#define T_STEPS 2048
#define BATCH   64
#define DIN     512
#define HDIM    512
#define G4      2048            // 4*H
#define M_ROWS  131072          // T*B
#define NBLK    128

typedef unsigned long long u64;
typedef unsigned int u32;

// Scratch (device globals: allocation-free contract)
// g_xproj layout: [t][cta(128)][batch(64)][q(4)][g(4)] fp32
__device__ float g_xproj[268435456];            // 1 GiB
__device__ __nv_bfloat16 g_xhi[67108864];       // X hi  (bf16)
__device__ __nv_bfloat16 g_xlo[67108864];       // X lo  (bf16)
__device__ __nv_bfloat16 g_wxthi[1048576];      // Wx^T hi [2048][512]
__device__ __nv_bfloat16 g_wxtlo[1048576];      // Wx^T lo
__device__ __half g_hf[2][32768];               // h state fp16 [buf][b*512+col]
__device__ unsigned long long g_arrive  = 0ULL;
__device__ unsigned long long g_release = 0ULL;

// ---------------------------------------------------------------------------
// PTX helpers
// ---------------------------------------------------------------------------
__device__ __forceinline__ u32 smem_u32(const void* p) {
    u32 a;
    asm("{ .reg .u64 t; cvta.to.shared.u64 t, %1; cvt.u32.u64 %0, t; }"
        : "=r"(a) : "l"(p));
    return a;
}
__device__ __forceinline__ void cpa16(u32 dst, const void* src) {
    asm volatile("cp.async.cg.shared.global [%0], [%1], 16;"
                 :: "r"(dst), "l"(src));
}
#define CP_COMMIT() asm volatile("cp.async.commit_group;" ::: "memory")

#define LDSM4(r0, r1, r2, r3, a) \
    asm volatile("ldmatrix.sync.aligned.m8n8.x4.shared.b16 {%0,%1,%2,%3}, [%4];" \
                 : "=r"(r0), "=r"(r1), "=r"(r2), "=r"(r3) : "r"(a))

#define MMA_BF16(c, a, b) \
    asm volatile("mma.sync.aligned.m16n8k16.row.col.f32.bf16.bf16.f32 " \
                 "{%0,%1,%2,%3}, {%4,%5,%6,%7}, {%8,%9}, {%0,%1,%2,%3};" \
                 : "+f"((c)[0]), "+f"((c)[1]), "+f"((c)[2]), "+f"((c)[3]) \
                 : "r"((a)[0]), "r"((a)[1]), "r"((a)[2]), "r"((a)[3]), \
                   "r"((b)[0]), "r"((b)[1]))

#define MMA_F16(c, a, b0r, b1r) \
    asm volatile("mma.sync.aligned.m16n8k16.row.col.f32.f16.f16.f32 " \
                 "{%0,%1,%2,%3}, {%4,%5,%6,%7}, {%8,%9}, {%0,%1,%2,%3};" \
                 : "+f"((c)[0]), "+f"((c)[1]), "+f"((c)[2]), "+f"((c)[3]) \
                 : "r"((a)[0]), "r"((a)[1]), "r"((a)[2]), "r"((a)[3]), \
                   "r"(b0r), "r"(b1r))

// ---------------------------------------------------------------------------
// Conversion kernels: fp32 -> bf16 hi/lo split (for x_proj GEMM)
// ---------------------------------------------------------------------------
__global__ __launch_bounds__(256) void convert_x(const float* __restrict__ X) {
    size_t i = (size_t)blockIdx.x * 256 + threadIdx.x;
    float4 v = ((const float4*)X)[i];
    __nv_bfloat16 h0 = __float2bfloat16(v.x);
    __nv_bfloat16 h1 = __float2bfloat16(v.y);
    __nv_bfloat16 h2 = __float2bfloat16(v.z);
    __nv_bfloat16 h3 = __float2bfloat16(v.w);
    __nv_bfloat16 l0 = __float2bfloat16(v.x - __bfloat162float(h0));
    __nv_bfloat16 l1 = __float2bfloat16(v.y - __bfloat162float(h1));
    __nv_bfloat16 l2 = __float2bfloat16(v.z - __bfloat162float(h2));
    __nv_bfloat16 l3 = __float2bfloat16(v.w - __bfloat162float(h3));
    __nv_bfloat162* ph = (__nv_bfloat162*)g_xhi;
    __nv_bfloat162* pl = (__nv_bfloat162*)g_xlo;
    ph[i * 2]     = __nv_bfloat162(h0, h1);
    ph[i * 2 + 1] = __nv_bfloat162(h2, h3);
    pl[i * 2]     = __nv_bfloat162(l0, l1);
    pl[i * 2 + 1] = __nv_bfloat162(l2, l3);
}

__global__ __launch_bounds__(256) void convert_w(const float* __restrict__ Wx) {
    int idx = blockIdx.x * 256 + threadIdx.x;
    int k = idx >> 11, g = idx & 2047;
    float v = Wx[idx];
    __nv_bfloat16 h = __float2bfloat16(v);
    __nv_bfloat16 l = __float2bfloat16(v - __bfloat162float(h));
    g_wxthi[(size_t)g * 512 + k] = h;
    g_wxtlo[(size_t)g * 512 + k] = l;
}

// ---------------------------------------------------------------------------
// Kernel 1: x_proj = X @ Wx + bx via mma.sync bf16, 3-term compensation.
// Epilogue writes the PERMUTED layout [t][cta][batch][q][g]. (Unchanged R5.)
// ---------------------------------------------------------------------------
#define TILE_B   10240
#define STAGE_B  (2 * TILE_B)

__device__ __forceinline__ void load_tile(
    u32 sA, u32 sB,
    const __nv_bfloat16* __restrict__ asrc,
    const __nv_bfloat16* __restrict__ bsrc,
    int kc, int tid)
{
#pragma unroll
    for (int p = 0; p < 2; p++) {
        int idx = tid + p * 256;
        int row = idx >> 2, seg = idx & 3;
        cpa16(sA + row * 80 + seg * 16,
              (const char*)(asrc + (size_t)row * 512 + kc) + seg * 16);
    }
#pragma unroll
    for (int p = 0; p < 2; p++) {
        int idx = tid + p * 256;
        int row = idx >> 2, seg = idx & 3;
        cpa16(sB + row * 80 + seg * 16,
              (const char*)(bsrc + (size_t)row * 512 + kc) + seg * 16);
    }
}

__global__ __launch_bounds__(256, 2) void gemm_xproj_hmma(
    const float* __restrict__ bias)
{
    __shared__ char smem[2 * STAGE_B];
    u32 sb = smem_u32(smem);

    const int tid  = threadIdx.x;
    const int lane = tid & 31;
    const int wid  = tid >> 5;
    const int m0w  = (wid & 3) * 32;
    const int n0w  = (wid >> 2) * 64;

    const int bn = blockIdx.x * 128;
    const int m0 = blockIdx.y * 128;

    const __nv_bfloat16* a_hi = g_xhi + (size_t)m0 * 512;
    const __nv_bfloat16* a_lo = g_xlo + (size_t)m0 * 512;
    const __nv_bfloat16* b_hi = g_wxthi + (size_t)bn * 512;
    const __nv_bfloat16* b_lo = g_wxtlo + (size_t)bn * 512;

    float acc[2][8][4];
#pragma unroll
    for (int mt = 0; mt < 2; mt++)
#pragma unroll
        for (int nt = 0; nt < 8; nt++)
#pragma unroll
            for (int r = 0; r < 4; r++) acc[mt][nt][r] = 0.f;

    load_tile(sb, sb + TILE_B, a_hi, b_hi, 0, tid);
    CP_COMMIT();

#pragma unroll 1
    for (int c = 0; c < 48; c++) {
        const int st = c & 1;
        if (c + 1 < 48) {
            const int cn = c + 1;
            const int s  = cn >> 4;
            const int kc = (cn & 15) * 32;
            const __nv_bfloat16* as = (s == 2) ? a_lo : a_hi;
            const __nv_bfloat16* bs = (s == 1) ? b_lo : b_hi;
            u32 base = sb + (u32)(st ^ 1) * STAGE_B;
            load_tile(base, base + TILE_B, as, bs, kc, tid);
            CP_COMMIT();
            asm volatile("cp.async.wait_group 1;" ::: "memory");
        } else {
            asm volatile("cp.async.wait_group 0;" ::: "memory");
        }
        __syncthreads();

        const u32 sA = sb + (u32)st * STAGE_B;
        const u32 sB = sA + TILE_B;

#pragma unroll
        for (int k16 = 0; k16 < 2; k16++) {
            const int kb = k16 * 16;
            u32 a_frag[2][4];
#pragma unroll
            for (int mt = 0; mt < 2; mt++) {
                u32 addr = sA + (u32)((m0w + mt * 16 + (lane & 15)) * 40
                                      + kb + (lane >> 4) * 8) * 2;
                LDSM4(a_frag[mt][0], a_frag[mt][1], a_frag[mt][2], a_frag[mt][3], addr);
            }
            u32 b_frag[8][2];
#pragma unroll
            for (int ntp = 0; ntp < 4; ntp++) {
                u32 addr = sB + (u32)((n0w + ntp * 16 + (lane & 15)) * 40
                                      + kb + (lane >> 4) * 8) * 2;
                u32 r0, r1, r2, r3;
                LDSM4(r0, r1, r2, r3, addr);
                b_frag[2 * ntp][0]     = r0;
                b_frag[2 * ntp][1]     = r2;
                b_frag[2 * ntp + 1][0] = r1;
                b_frag[2 * ntp + 1][1] = r3;
            }
#pragma unroll
            for (int mt = 0; mt < 2; mt++)
#pragma unroll
                for (int nt = 0; nt < 8; nt++)
                    MMA_BF16(acc[mt][nt], a_frag[mt], b_frag[nt]);
        }
        __syncthreads();
    }

    const int mrow  = m0 + m0w + (lane >> 2);
    const int ncol0 = bn + n0w + (lane & 3) * 2;
#pragma unroll
    for (int mt = 0; mt < 2; mt++) {
#pragma unroll
        for (int nt = 0; nt < 8; nt++) {
            const int col = ncol0 + nt * 8;
            const float2 bs = __ldg((const float2*)(bias + col));
            const int g = col >> 9;
            const int hcol = col & 511;
            const size_t cb = (size_t)(hcol >> 2) * 1024 + (hcol & 3) * 4 + g;
            const int rA = mrow + mt * 16;
            const int rB = rA + 8;
            const size_t baseA = (size_t)(rA >> 6) * 131072 + (rA & 63) * 16;
            const size_t baseB = (size_t)(rB >> 6) * 131072 + (rB & 63) * 16;
            g_xproj[baseA + cb]     = acc[mt][nt][0] + bs.x;
            g_xproj[baseA + cb + 4] = acc[mt][nt][1] + bs.y;
            g_xproj[baseB + cb]     = acc[mt][nt][2] + bs.x;
            g_xproj[baseB + cb + 4] = acc[mt][nt][3] + bs.y;
        }
    }
}

// ---------------------------------------------------------------------------
// Kernel 2: persistent recurrence. h fp16 single-plane; Wh fp16 hi/lo held in
// REGISTERS (128/warp). Split-K over warp groups; warp tile m16 x n16.
// ---------------------------------------------------------------------------
#define APB 1040          // A plane row pitch bytes (512 fp16 + 8 pad)
#define SM_A    0         // 64*1040 = 66560
#define SM_RED  66560     // 4096: [frag(2)][warp(4)][lane(32)] float4
#define SM_WST  70656     // W staging: 2 planes * 16*1040 = 33280 (startup)
#define SM_TOTAL 103936

__device__ __forceinline__ void grid_barrier() {
    __syncthreads();
    if (threadIdx.x == 0) {
        __threadfence();
        unsigned long long t = atomicAdd(&g_arrive, 1ULL) + 1ULL;
        unsigned long long n = (unsigned long long)NBLK;
        unsigned long long target = ((t + n - 1ULL) / n) * n;
        if (t == target) {
            atomicMax(&g_release, target);
        } else {
            unsigned long long r;
            do {
                asm volatile("ld.volatile.global.u64 %0, [%1];"
                             : "=l"(r) : "l"(&g_release));
            } while (r < target);
        }
        __threadfence();
    }
    __syncthreads();
}

__global__ __launch_bounds__(256, 1) void lstm_seq(
    const float* __restrict__ Wh,   // [512][2048]
    const float* __restrict__ bh,   // [2048]
    float* __restrict__ out)        // [2][64][512]
{
    extern __shared__ char smem[];
    u32 sb = smem_u32(smem);

    const int tid  = threadIdx.x;
    const int cta  = blockIdx.x;
    const int c0   = cta * 4;
    const int lane = tid & 31;
    const int wid  = tid >> 5;
    const int grp  = wid >> 2;     // k-half: 0 -> k[0:256), 1 -> k[256:512)
    const int mw   = wid & 3;      // m-tile (16 batches)

    // --- Stage Wh slice into smem fp16 hi/lo, rows n = q*4+g, k contiguous
    for (int idx = tid; idx < 16 * 512; idx += 256) {
        int n = idx & 15, k = idx >> 4;
        int q = n >> 2, g = n & 3;
        float v = Wh[(size_t)k * G4 + g * HDIM + c0 + q];
        __half h = __float2half_rn(v);
        __half l = __float2half_rn(v - __half2float(h));
        *(__half*)(smem + SM_WST + n * APB + k * 2)         = h;
        *(__half*)(smem + SM_WST + 16640 + n * APB + k * 2) = l;
    }
    __syncthreads();

    // --- B fragments into registers (held for the whole run)
    u32 bhi[16][4], blo[16][4];
    {
        const u32 wrow_h = sb + SM_WST + (u32)(lane & 15) * APB
                         + (u32)grp * 512 + (u32)(lane >> 4) * 16;
        const u32 wrow_l = wrow_h + 16640;
#pragma unroll
        for (int kk = 0; kk < 16; kk++) {
            LDSM4(bhi[kk][0], bhi[kk][1], bhi[kk][2], bhi[kk][3], wrow_h + kk * 32);
            LDSM4(blo[kk][0], blo[kk][1], blo[kk][2], blo[kk][3], wrow_l + kk * 32);
        }
    }

    // --- Per-lane state identity (meaningful for grp 0)
    const int q   = ((lane >> 1) & 1) + 2 * (lane & 1);
    const int col = c0 + q;
    const int b0  = mw * 16 + (lane >> 2);
    const int b1  = b0 + 8;

    float4 bhv;
    bhv.x = bh[0 * HDIM + col];
    bhv.y = bh[1 * HDIM + col];
    bhv.z = bh[2 * HDIM + col];
    bhv.w = bh[3 * HDIM + col];

    // Zero h buffer 0 (32768 halfs = 16384 u32; 32768 threads chip-wide)
    {
        int gt = cta * 256 + tid;
        if (gt < 16384) ((u32*)g_hf[0])[gt] = 0u;
    }

    grid_barrier();

    float cst0 = 0.f, cst1 = 0.f;
    float hs0 = 0.f, hs1 = 0.f, cs0 = 0.f, cs1 = 0.f;

    const u32 arow = sb + SM_A + (u32)(mw * 16 + (lane & 15)) * APB
                   + (u32)grp * 512 + (u32)(lane >> 4) * 16;
    const u32 red_st = sb + SM_RED + (u32)mw * 512 + (u32)lane * 16;

    for (int t = 0; t < T_STEPS; t++) {
        const int rb = t & 1;
        const __half* src = g_hf[rb];

        // Broadcast h (fp16, 64 KB) into smem via cp.async
#pragma unroll
        for (int i = 0; i < 16; i++) {
            int u = tid + i * 256;
            int row = u >> 6, seg = u & 63;
            cpa16(sb + SM_A + (u32)row * APB + (u32)seg * 16,
                  (const char*)src + row * 1024 + seg * 16);
        }
        CP_COMMIT();

        // x_proj gates (coalesced float4; overlaps cp.async)
        float4 x0, x1;
        x0.x = x0.y = x0.z = x0.w = 0.f; x1 = x0;
        if (grp == 0) {
            const float* xb = g_xproj + (size_t)t * 131072 + cta * 1024
                            + b0 * 16 + q * 4;
            x0 = *(const float4*)xb;
            x1 = *(const float4*)(xb + 128);
        }

        asm volatile("cp.async.wait_group 0;" ::: "memory");
        __syncthreads();

        // MMA: m16n16, K-half; B from registers
        float acc0[4] = {0.f, 0.f, 0.f, 0.f};
        float acc1[4] = {0.f, 0.f, 0.f, 0.f};
#pragma unroll
        for (int kk = 0; kk < 16; kk++) {
            u32 a[4];
            LDSM4(a[0], a[1], a[2], a[3], arow + kk * 32);
            MMA_F16(acc0, a, bhi[kk][0], bhi[kk][2]);
            MMA_F16(acc0, a, blo[kk][0], blo[kk][2]);
            MMA_F16(acc1, a, bhi[kk][1], bhi[kk][3]);
            MMA_F16(acc1, a, blo[kk][1], blo[kk][3]);
        }

        // Split-K reduction: group 1 stores, group 0 adds
        if (grp == 1) {
            float4 v0 = {acc0[0], acc0[1], acc0[2], acc0[3]};
            float4 v1 = {acc1[0], acc1[1], acc1[2], acc1[3]};
            *(float4*)(smem + (red_st - sb))          = v0;
            *(float4*)(smem + (red_st - sb) + 2048)   = v1;
        }
        __syncthreads();

        if (grp == 0) {
            float4 r0 = *(const float4*)(smem + (red_st - sb));
            float4 r1 = *(const float4*)(smem + (red_st - sb) + 2048);
            acc0[0] += r0.x; acc0[1] += r0.y; acc0[2] += r0.z; acc0[3] += r0.w;
            acc1[0] += r1.x; acc1[1] += r1.y; acc1[2] += r1.z; acc1[3] += r1.w;

            // Pair exchange: even keeps frag0/sends frag1; odd keeps frag1/sends frag0
            const bool odd = (lane & 1);
            float rv[4];
#pragma unroll
            for (int i = 0; i < 4; i++) {
                float send = odd ? acc0[i] : acc1[i];
                rv[i] = __shfl_xor_sync(0xffffffffu, send, 1);
            }

            float gi0, gf0, go0, gz0, gi1, gf1, go1, gz1;
            if (!odd) {
                gi0 = acc0[0]; gf0 = acc0[1]; go0 = rv[0];  gz0 = rv[1];
                gi1 = acc0[2]; gf1 = acc0[3]; go1 = rv[2];  gz1 = rv[3];
            } else {
                gi0 = rv[0];   gf0 = rv[1];   go0 = acc1[0]; gz0 = acc1[1];
                gi1 = rv[2];   gf1 = rv[3];   go1 = acc1[2]; gz1 = acc1[3];
            }

            gi0 += x0.x + bhv.x; gf0 += x0.y + bhv.y;
            go0 += x0.z + bhv.z; gz0 += x0.w + bhv.w;
            gi1 += x1.x + bhv.x; gf1 += x1.y + bhv.y;
            go1 += x1.z + bhv.z; gz1 += x1.w + bhv.w;

            const float iv0 = 1.f / (1.f + __expf(-gi0));
            const float fv0 = 1.f / (1.f + __expf(-gf0));
            const float ov0 = 1.f / (1.f + __expf(-go0));
            const float zv0 = 1.f - 2.f / (__expf(2.f * gz0) + 1.f);
            cst0 = fmaf(iv0, zv0, fv0 * cst0);
            const float h0 = ov0 * (1.f - 2.f / (__expf(2.f * cst0) + 1.f));

            const float iv1 = 1.f / (1.f + __expf(-gi1));
            const float fv1 = 1.f / (1.f + __expf(-gf1));
            const float ov1 = 1.f / (1.f + __expf(-go1));
            const float zv1 = 1.f - 2.f / (__expf(2.f * gz1) + 1.f);
            cst1 = fmaf(iv1, zv1, fv1 * cst1);
            const float h1 = ov1 * (1.f - 2.f / (__expf(2.f * cst1) + 1.f));

            hs0 += h0; cs0 += cst0;
            hs1 += h1; cs1 += cst1;

            const int nb = rb ^ 1;
            g_hf[nb][b0 * HDIM + col] = __float2half_rn(h0);
            g_hf[nb][b1 * HDIM + col] = __float2half_rn(h1);
        }

        grid_barrier();
    }

    if (grp == 0) {
        const float inv = 1.0f / (float)T_STEPS;
        out[b0 * HDIM + col]                = hs0 * inv;
        out[BATCH * HDIM + b0 * HDIM + col] = cs0 * inv;
        out[b1 * HDIM + col]                = hs1 * inv;
        out[BATCH * HDIM + b1 * HDIM + col] = cs1 * inv;
    }
}

// ---------------------------------------------------------------------------
extern "C" void kernel_launch(void* const* d_in, const int* in_sizes, int n_in,
                              void* d_out, int out_size) {
    const float* X  = (const float*)d_in[0];
    const float* Wx = (const float*)d_in[1];
    const float* bx = (const float*)d_in[2];
    const float* Wh = (const float*)d_in[3];
    const float* bh = (const float*)d_in[4];
    float* out = (float*)d_out;

    cudaFuncSetAttribute(lstm_seq,
                         cudaFuncAttributeMaxDynamicSharedMemorySize, SM_TOTAL);

    convert_x<<<65536, 256>>>(X);
    convert_w<<<4096, 256>>>(Wx);

    dim3 gemm_grid(16, 1024);
    gemm_xproj_hmma<<<gemm_grid, 256>>>(bx);

    lstm_seq<<<NBLK, 256, SM_TOTAL>>>(Wh, bh, out);
}